// round 10
// baseline (speedup 1.0000x reference)
#include <cuda_runtime.h>
#include <cstdint>

// ---------------- problem constants ----------------
#define B_   2
#define S_   2048
#define E_   2048
#define H_   16
#define HKV_ 8
#define D_   64
#define M_   (B_*S_)   // 4096 rows for all GEMMs

__device__ float g_q [(size_t)B_*H_  *2*S_*D_];   // [b][h][comp][s][d]
__device__ float g_k [(size_t)B_*HKV_*2*S_*D_];   // [b][hk][comp][s][d]
__device__ float g_v [(size_t)B_*HKV_*S_*2*D_];   // [b][hk][s][128]
__device__ float g_a1[(size_t)B_*H_*S_*2*D_];     // [b][h][s][128]
__device__ float g_a2[(size_t)B_*H_*S_*2*D_];
__device__ float g_ac[(size_t)B_*S_*E_];          // combined attn, [(b,s)][h*128+c]
__device__ float g_lam;

__device__ __constant__ float kLambdaInit   = 0.7836057665316245f;
__device__ __constant__ float kOneMinusLI   = 0.2163942334683755f;
#define SCALE_  0.125f
#define NEGBIG  (-1e30f)

// ---------------- packed f32x2 helpers (Blackwell FFMA2 path) ----------------
__device__ __forceinline__ unsigned long long pack2(float lo, float hi) {
    unsigned long long r;
    asm("mov.b64 %0, {%1,%2};" : "=l"(r) : "f"(lo), "f"(hi));
    return r;
}
__device__ __forceinline__ float2 unpack2(unsigned long long v) {
    float2 r;
    asm("mov.b64 {%0,%1}, %2;" : "=f"(r.x), "=f"(r.y) : "l"(v));
    return r;
}
__device__ __forceinline__ unsigned long long fma2(unsigned long long a,
                                                   unsigned long long b,
                                                   unsigned long long c) {
    unsigned long long d;
    asm("fma.rn.f32x2 %0, %1, %2, %3;" : "=l"(d) : "l"(a), "l"(b), "l"(c));
    return d;
}
__device__ __forceinline__ unsigned long long mul2(unsigned long long a,
                                                   unsigned long long b) {
    unsigned long long d;
    asm("mul.rn.f32x2 %0, %1, %2;" : "=l"(d) : "l"(a), "l"(b));
    return d;
}

// ============================================================================
// SGEMM: C[m][n] = sum_k A[m][k] * W[n][k]   (A row-major MxK, W row-major NxK)
// 128x128 tile, BK=16, 256 threads, 8x8 micro-tile, f32x2 packed FMA.
// MODE 0: plain store to C (A taken from g_ac)       -> final Wo projection
// MODE 1: rotary epilogue, scatter to g_q            -> Q projection (N=2048)
// MODE 2: rotary epilogue, scatter to g_k            -> K projection (N=1024)
// MODE 3: plain scatter to g_v [b][hk][s][128]       -> V projection (N=1024)
// ============================================================================
template<int MODE, int N>
__global__ __launch_bounds__(256)
void sgemm_k(const float* __restrict__ A, const float* __restrict__ W,
             float* __restrict__ C,
             const float* __restrict__ cosp, const float* __restrict__ sinp)
{
    constexpr int K = E_;
    __shared__ float As[16][132];
    __shared__ float Ws[16][132];

    const float* Ap = (MODE == 0) ? (const float*)g_ac : A;

    const int tid = threadIdx.x;
    const int tx  = tid & 15;        // 0..15  -> 8 output cols
    const int ty  = tid >> 4;        // 0..15  -> 8 output rows
    const int row0 = blockIdx.y * 128;
    const int col0 = blockIdx.x * 128;

    unsigned long long acc[4][8];    // row-pairs (2 rows packed) x 8 cols
    #pragma unroll
    for (int i = 0; i < 4; ++i)
        #pragma unroll
        for (int j = 0; j < 8; ++j) acc[i][j] = 0ULL;

    for (int k0 = 0; k0 < K; k0 += 16) {
        #pragma unroll
        for (int it = 0; it < 2; ++it) {
            int f  = tid + it * 256;          // 0..511
            int r  = f >> 2;                  // 0..127
            int c4 = (f & 3) * 4;             // 0,4,8,12
            float4 av = *reinterpret_cast<const float4*>(
                Ap + (size_t)(row0 + r) * K + k0 + c4);
            As[c4+0][r] = av.x; As[c4+1][r] = av.y;
            As[c4+2][r] = av.z; As[c4+3][r] = av.w;
            float4 wv = *reinterpret_cast<const float4*>(
                W + (size_t)(col0 + r) * K + k0 + c4);
            Ws[c4+0][r] = wv.x; Ws[c4+1][r] = wv.y;
            Ws[c4+2][r] = wv.z; Ws[c4+3][r] = wv.w;
        }
        __syncthreads();

        #pragma unroll
        for (int kk = 0; kk < 16; ++kk) {
            ulonglong2 a01 = *reinterpret_cast<const ulonglong2*>(&As[kk][ty*8]);
            ulonglong2 a23 = *reinterpret_cast<const ulonglong2*>(&As[kk][ty*8+4]);
            float4 w0 = *reinterpret_cast<const float4*>(&Ws[kk][tx*8]);
            float4 w1 = *reinterpret_cast<const float4*>(&Ws[kk][tx*8+4]);
            unsigned long long ar[4] = {a01.x, a01.y, a23.x, a23.y};
            float wf[8] = {w0.x, w0.y, w0.z, w0.w, w1.x, w1.y, w1.z, w1.w};
            #pragma unroll
            for (int j = 0; j < 8; ++j) {
                unsigned long long wb = pack2(wf[j], wf[j]);
                #pragma unroll
                for (int i2 = 0; i2 < 4; ++i2)
                    acc[i2][j] = fma2(ar[i2], wb, acc[i2][j]);
            }
        }
        __syncthreads();
    }

    // unpack into row-major register tile
    float Cv[8][8];
    #pragma unroll
    for (int i2 = 0; i2 < 4; ++i2)
        #pragma unroll
        for (int j = 0; j < 8; ++j) {
            float2 t = unpack2(acc[i2][j]);
            Cv[2*i2  ][j] = t.x;
            Cv[2*i2+1][j] = t.y;
        }

    #pragma unroll
    for (int i = 0; i < 8; ++i) {
        const int grow = row0 + ty * 8 + i;
        if constexpr (MODE == 0) {
            #pragma unroll
            for (int j = 0; j < 8; j += 4) {
                float4 o = make_float4(Cv[i][j], Cv[i][j+1], Cv[i][j+2], Cv[i][j+3]);
                *reinterpret_cast<float4*>(C + (size_t)grow * N + col0 + tx*8 + j) = o;
            }
        } else {
            const int b = grow >> 11;           // /S_
            const int s = grow & (S_ - 1);
            const int gcol0 = col0 + tx * 8;    // all 8 cols within one 64-head
            if constexpr (MODE == 1 || MODE == 2) {
                const int head = gcol0 >> 6;
                const int d0   = gcol0 & 63;    // even
                const int hh   = head >> 1;
                const int comp = head & 1;
                float* dst;
                if constexpr (MODE == 1)
                    dst = g_q + ((((size_t)b*H_   + hh)*2 + comp)*S_ + s)*D_ + d0;
                else
                    dst = g_k + ((((size_t)b*HKV_ + hh)*2 + comp)*S_ + s)*D_ + d0;
                const float* cr = cosp + (size_t)s * 32;
                const float* sr = sinp + (size_t)s * 32;
                #pragma unroll
                for (int jp = 0; jp < 4; ++jp) {
                    float c  = cr[(d0 >> 1) + jp];
                    float sn = sr[(d0 >> 1) + jp];
                    float x1 = Cv[i][2*jp], x2 = Cv[i][2*jp+1];
                    dst[2*jp  ] = x1*c  - x2*sn;
                    dst[2*jp+1] = x1*sn + x2*c;
                }
            } else {  // MODE 3: V, cols = hk*128 + c
                const int hk = gcol0 >> 7;
                const int cc = gcol0 & 127;
                float* dst = g_v + (((size_t)b*HKV_ + hk)*S_ + s)*128 + cc;
                #pragma unroll
                for (int j = 0; j < 8; j += 4)
                    *reinterpret_cast<float4*>(dst + j) =
                        make_float4(Cv[i][j], Cv[i][j+1], Cv[i][j+2], Cv[i][j+3]);
            }
        }
    }
}

// ============================================================================
// Causal flash attention, fp32, one (b, h, component) per blockIdx.(z,y).
// BM=64 queries, BN=64 keys per tile, D=64, DV=128, 256 threads.
// ============================================================================
#define QST 68
#define VST 132
#define FLASH_SMEM_FLOATS (64*QST*3 + 64*VST)
#define FLASH_SMEM_BYTES  (FLASH_SMEM_FLOATS * 4)

__global__ __launch_bounds__(256)
void flash_k()
{
    extern __shared__ float sm[];
    float* Qs = sm;                         // [d][r]   64 x 68
    float* Ks = sm + 64*QST;                // [d][c]   64 x 68
    float* Vs = sm + 2*64*QST;              // [c][cv]  64 x 132
    float* Ps = sm + 2*64*QST + 64*VST;     // [r][c]   64 x 68

    const int qt = blockIdx.x;              // 0..31
    const int h  = blockIdx.y >> 1;
    const int j  = blockIdx.y & 1;
    const int b  = blockIdx.z;

    const float* qp = g_q + ((((size_t)b*H_   + h     )*2 + j)*S_ + (size_t)qt*64)*D_;
    const float* kp = g_k + ((((size_t)b*HKV_ + (h>>1))*2 + j)*S_)*D_;
    const float* vp = g_v + ((( (size_t)b*HKV_ + (h>>1))*S_))*128;
    float* op = (j == 0 ? g_a1 : g_a2) + (((size_t)b*H_ + h)*S_ + (size_t)qt*64)*128;

    const int tid = threadIdx.x;
    const int tx  = tid & 15;   // key cols 4*tx..   / out cols 8*tx..
    const int ty  = tid >> 4;   // query rows 4*ty..

    // load Q tile transposed: Qs[d][r]
    #pragma unroll
    for (int it = 0; it < 4; ++it) {
        int f = tid + it*256;         // 0..1023
        int r = f >> 4, d4 = (f & 15) * 4;
        float4 v = *reinterpret_cast<const float4*>(qp + (size_t)r*64 + d4);
        Qs[(d4+0)*QST + r] = v.x; Qs[(d4+1)*QST + r] = v.y;
        Qs[(d4+2)*QST + r] = v.z; Qs[(d4+3)*QST + r] = v.w;
    }

    unsigned long long o2[4][4];    // rows(4) x col-pairs(4) of 128-wide output
    #pragma unroll
    for (int i = 0; i < 4; ++i)
        #pragma unroll
        for (int j2 = 0; j2 < 4; ++j2) o2[i][j2] = 0ULL;
    float m[4], l[4];
    #pragma unroll
    for (int i = 0; i < 4; ++i) { m[i] = NEGBIG; l[i] = 0.0f; }

    for (int n = 0; n <= qt; ++n) {
        __syncthreads();   // protect Ks/Vs/Ps reuse
        #pragma unroll
        for (int it = 0; it < 4; ++it) {
            int f = tid + it*256;
            int r = f >> 4, d4 = (f & 15) * 4;
            float4 v = *reinterpret_cast<const float4*>(kp + (size_t)(n*64 + r)*64 + d4);
            Ks[(d4+0)*QST + r] = v.x; Ks[(d4+1)*QST + r] = v.y;
            Ks[(d4+2)*QST + r] = v.z; Ks[(d4+3)*QST + r] = v.w;
        }
        #pragma unroll
        for (int it = 0; it < 8; ++it) {
            int f = tid + it*256;
            int r = f >> 5, c4 = (f & 31) * 4;
            *reinterpret_cast<float4*>(&Vs[r*VST + c4]) =
                *reinterpret_cast<const float4*>(vp + (size_t)(n*64 + r)*128 + c4);
        }
        __syncthreads();

        // S = Q K^T  (rows 4*ty.., cols 4*tx..), packed pairs along cols
        unsigned long long s2[4][2];
        #pragma unroll
        for (int i = 0; i < 4; ++i) { s2[i][0] = 0ULL; s2[i][1] = 0ULL; }
        #pragma unroll 4
        for (int d = 0; d < 64; ++d) {
            ulonglong2 kk2 = *reinterpret_cast<const ulonglong2*>(&Ks[d*QST + tx*4]);
            float4 qv = *reinterpret_cast<const float4*>(&Qs[d*QST + ty*4]);
            float qf[4] = {qv.x, qv.y, qv.z, qv.w};
            #pragma unroll
            for (int i = 0; i < 4; ++i) {
                unsigned long long qb = pack2(qf[i], qf[i]);
                s2[i][0] = fma2(qb, kk2.x, s2[i][0]);
                s2[i][1] = fma2(qb, kk2.y, s2[i][1]);
            }
        }

        const int qi0 = qt*64 + ty*4;
        const int kj0 = n *64 + tx*4;
        float sv[4][4];
        #pragma unroll
        for (int i = 0; i < 4; ++i) {
            float2 t0 = unpack2(s2[i][0]);
            float2 t1 = unpack2(s2[i][1]);
            sv[i][0] = t0.x * SCALE_; sv[i][1] = t0.y * SCALE_;
            sv[i][2] = t1.x * SCALE_; sv[i][3] = t1.y * SCALE_;
            #pragma unroll
            for (int jj = 0; jj < 4; ++jj)
                if (kj0 + jj > qi0 + i) sv[i][jj] = NEGBIG;
        }

        // online softmax (row stats reduced across the 16 tx lanes)
        #pragma unroll
        for (int i = 0; i < 4; ++i) {
            float mx = fmaxf(fmaxf(sv[i][0], sv[i][1]), fmaxf(sv[i][2], sv[i][3]));
            mx = fmaxf(mx, __shfl_xor_sync(0xffffffffu, mx, 8));
            mx = fmaxf(mx, __shfl_xor_sync(0xffffffffu, mx, 4));
            mx = fmaxf(mx, __shfl_xor_sync(0xffffffffu, mx, 2));
            mx = fmaxf(mx, __shfl_xor_sync(0xffffffffu, mx, 1));
            float mn   = fmaxf(m[i], mx);
            float corr = __expf(m[i] - mn);
            m[i] = mn;
            float srow = 0.0f;
            #pragma unroll
            for (int jj = 0; jj < 4; ++jj) {
                float p = __expf(sv[i][jj] - mn);
                Ps[(ty*4 + i)*QST + tx*4 + jj] = p;
                srow += p;
            }
            srow += __shfl_xor_sync(0xffffffffu, srow, 8);
            srow += __shfl_xor_sync(0xffffffffu, srow, 4);
            srow += __shfl_xor_sync(0xffffffffu, srow, 2);
            srow += __shfl_xor_sync(0xffffffffu, srow, 1);
            l[i] = l[i] * corr + srow;
            unsigned long long c2 = pack2(corr, corr);
            #pragma unroll
            for (int j2 = 0; j2 < 4; ++j2) o2[i][j2] = mul2(o2[i][j2], c2);
        }
        __syncthreads();

        // O += P V
        #pragma unroll 2
        for (int c = 0; c < 64; ++c) {
            ulonglong2 v01 = *reinterpret_cast<const ulonglong2*>(&Vs[c*VST + tx*8]);
            ulonglong2 v23 = *reinterpret_cast<const ulonglong2*>(&Vs[c*VST + tx*8 + 4]);
            unsigned long long vv[4] = {v01.x, v01.y, v23.x, v23.y};
            #pragma unroll
            for (int i = 0; i < 4; ++i) {
                float p = Ps[(ty*4 + i)*QST + c];
                unsigned long long pb = pack2(p, p);
                #pragma unroll
                for (int j2 = 0; j2 < 4; ++j2)
                    o2[i][j2] = fma2(pb, vv[j2], o2[i][j2]);
            }
        }
    }

    #pragma unroll
    for (int i = 0; i < 4; ++i) {
        float inv = 1.0f / l[i];
        float2 p0 = unpack2(o2[i][0]), p1 = unpack2(o2[i][1]);
        float2 p2 = unpack2(o2[i][2]), p3 = unpack2(o2[i][3]);
        float4 w0 = make_float4(p0.x*inv, p0.y*inv, p1.x*inv, p1.y*inv);
        float4 w1 = make_float4(p2.x*inv, p2.y*inv, p3.x*inv, p3.y*inv);
        *reinterpret_cast<float4*>(op + (size_t)(ty*4 + i)*128 + tx*8    ) = w0;
        *reinterpret_cast<float4*>(op + (size_t)(ty*4 + i)*128 + tx*8 + 4) = w1;
    }
}

// ============================================================================
// lambda scalar: exp(sum q1*k1) - exp(sum q2*k2) + lambda_init
// ============================================================================
__global__ void lam_k(const float* __restrict__ q1, const float* __restrict__ k1,
                      const float* __restrict__ q2, const float* __restrict__ k2)
{
    int t = threadIdx.x;
    float s1 = q1[t]*k1[t] + q1[t+32]*k1[t+32];
    float s2 = q2[t]*k2[t] + q2[t+32]*k2[t+32];
    #pragma unroll
    for (int off = 16; off; off >>= 1) {
        s1 += __shfl_xor_sync(0xffffffffu, s1, off);
        s2 += __shfl_xor_sync(0xffffffffu, s2, off);
    }
    if (t == 0) g_lam = expf(s1) - expf(s2) + kLambdaInit;
}

// ============================================================================
// combine: a = a1 - lam*a2; RMSNorm over 128; * subln_w * (1-lambda_init);
// scatter into [(b,s)][h*128+c] for the output GEMM. One warp per (b,h,s) row.
// ============================================================================
__global__ __launch_bounds__(256)
void combine_k(const float* __restrict__ subw)
{
    const int warp = threadIdx.x >> 5;
    const int lane = threadIdx.x & 31;
    const size_t r = (size_t)blockIdx.x * 8 + warp;     // over B*H*S
    const float lam = g_lam;

    float4 a1 = *reinterpret_cast<const float4*>(&g_a1[r*128 + lane*4]);
    float4 a2 = *reinterpret_cast<const float4*>(&g_a2[r*128 + lane*4]);
    float v0 = a1.x - lam*a2.x;
    float v1 = a1.y - lam*a2.y;
    float v2 = a1.z - lam*a2.z;
    float v3 = a1.w - lam*a2.w;

    float ss = v0*v0 + v1*v1 + v2*v2 + v3*v3;
    #pragma unroll
    for (int off = 16; off; off >>= 1)
        ss += __shfl_xor_sync(0xffffffffu, ss, off);

    float sc = rsqrtf(ss * (1.0f/128.0f) + 1e-5f) * kOneMinusLI;
    float4 w = *reinterpret_cast<const float4*>(&subw[lane*4]);

    const int s  = (int)(r & (S_ - 1));
    const int bh = (int)(r >> 11);
    const int b  = bh >> 4;
    const int hh = bh & 15;

    float4 o = make_float4(v0*sc*w.x, v1*sc*w.y, v2*sc*w.z, v3*sc*w.w);
    *reinterpret_cast<float4*>(&g_ac[((size_t)(b*S_ + s))*E_ + hh*128 + lane*4]) = o;
}

// ============================================================================
// launcher
// ============================================================================
extern "C" void kernel_launch(void* const* d_in, const int* in_sizes, int n_in,
                              void* d_out, int out_size)
{
    const float* x    = (const float*)d_in[0];
    const float* cosp = (const float*)d_in[1];
    const float* sinp = (const float*)d_in[2];
    const float* Wq   = (const float*)d_in[3];
    const float* Wk   = (const float*)d_in[4];
    const float* Wv   = (const float*)d_in[5];
    const float* Wo   = (const float*)d_in[6];
    const float* lq1  = (const float*)d_in[7];
    const float* lk1  = (const float*)d_in[8];
    const float* lq2  = (const float*)d_in[9];
    const float* lk2  = (const float*)d_in[10];
    const float* subw = (const float*)d_in[11];
    float* out = (float*)d_out;

    cudaFuncSetAttribute(flash_k, cudaFuncAttributeMaxDynamicSharedMemorySize,
                         FLASH_SMEM_BYTES);

    // projections (rotary fused into Q/K epilogues, layout scatter fused into all)
    sgemm_k<1, 2048><<<dim3(16, 32), 256>>>(x, Wq, nullptr, cosp, sinp);
    sgemm_k<2, 1024><<<dim3( 8, 32), 256>>>(x, Wk, nullptr, cosp, sinp);
    sgemm_k<3, 1024><<<dim3( 8, 32), 256>>>(x, Wv, nullptr, nullptr, nullptr);

    lam_k<<<1, 32>>>(lq1, lk1, lq2, lk2);

    // 64 causal flash instances: (qtile=32, h*2+comp=32, b=2)
    flash_k<<<dim3(32, 32, 2), 256, FLASH_SMEM_BYTES>>>();

    // differential combine + RMSNorm
    combine_k<<<(B_*H_*S_)/8, 256>>>(subw);

    // output projection
    sgemm_k<0, 2048><<<dim3(16, 32), 256>>>(nullptr, Wo, out, nullptr, nullptr);
}

// round 12
// speedup vs baseline: 1.0059x; 1.0059x over previous
#include <cuda_runtime.h>
#include <cstdint>

// ---------------- problem constants ----------------
#define B_   2
#define S_   2048
#define E_   2048
#define H_   16
#define HKV_ 8
#define D_   64
#define M_   (B_*S_)   // 4096 rows for all GEMMs

__device__ float g_q [(size_t)B_*H_  *2*S_*D_];   // [b][h][comp][s][d]
__device__ float g_k [(size_t)B_*HKV_*2*S_*D_];   // [b][hk][comp][s][d]
__device__ float g_v [(size_t)B_*HKV_*S_*2*D_];   // [b][hk][s][128]
__device__ float g_a1[(size_t)B_*H_*S_*2*D_];     // [b][h][s][128]
__device__ float g_a2[(size_t)B_*H_*S_*2*D_];
__device__ float g_ac[(size_t)B_*S_*E_];          // combined attn, [(b,s)][h*128+c]
__device__ float g_lam;

__device__ __constant__ float kLambdaInit   = 0.7836057665316245f;
__device__ __constant__ float kOneMinusLI   = 0.2163942334683755f;
#define SCALE_  0.125f
#define NEGBIG  (-1e30f)

// ---------------- packed f32x2 helpers (Blackwell FFMA2 path) ----------------
__device__ __forceinline__ unsigned long long pack2(float lo, float hi) {
    unsigned long long r;
    asm("mov.b64 %0, {%1,%2};" : "=l"(r) : "f"(lo), "f"(hi));
    return r;
}
__device__ __forceinline__ float2 unpack2(unsigned long long v) {
    float2 r;
    asm("mov.b64 {%0,%1}, %2;" : "=f"(r.x), "=f"(r.y) : "l"(v));
    return r;
}
__device__ __forceinline__ unsigned long long fma2(unsigned long long a,
                                                   unsigned long long b,
                                                   unsigned long long c) {
    unsigned long long d;
    asm("fma.rn.f32x2 %0, %1, %2, %3;" : "=l"(d) : "l"(a), "l"(b), "l"(c));
    return d;
}
__device__ __forceinline__ unsigned long long mul2(unsigned long long a,
                                                   unsigned long long b) {
    unsigned long long d;
    asm("mul.rn.f32x2 %0, %1, %2;" : "=l"(d) : "l"(a), "l"(b));
    return d;
}

// ============================================================================
// SGEMM: C[m][n] = sum_k A[m][k] * W[n][k]   (A row-major MxK, W row-major NxK)
// 128x128 tile, BK=16, 256 threads, 8x8 micro-tile, f32x2 packed FMA.
// MODE 0: plain store to C (A taken from g_ac)       -> final Wo projection
// MODE 1: rotary epilogue, scatter to g_q            -> Q projection (N=2048)
// MODE 2: rotary epilogue, scatter to g_k            -> K projection (N=1024)
// MODE 3: plain scatter to g_v [b][hk][s][128]       -> V projection (N=1024)
// ============================================================================
template<int MODE, int N>
__global__ __launch_bounds__(256)
void sgemm_k(const float* __restrict__ A, const float* __restrict__ W,
             float* __restrict__ C,
             const float* __restrict__ cosp, const float* __restrict__ sinp)
{
    constexpr int K = E_;
    __shared__ float As[16][132];
    __shared__ float Ws[16][132];

    const float* Ap = (MODE == 0) ? (const float*)g_ac : A;

    const int tid = threadIdx.x;
    const int tx  = tid & 15;        // 0..15  -> 8 output cols
    const int ty  = tid >> 4;        // 0..15  -> 8 output rows
    const int row0 = blockIdx.y * 128;
    const int col0 = blockIdx.x * 128;

    unsigned long long acc[4][8];    // row-pairs (2 rows packed) x 8 cols
    #pragma unroll
    for (int i = 0; i < 4; ++i)
        #pragma unroll
        for (int j = 0; j < 8; ++j) acc[i][j] = 0ULL;

    for (int k0 = 0; k0 < K; k0 += 16) {
        #pragma unroll
        for (int it = 0; it < 2; ++it) {
            int f  = tid + it * 256;          // 0..511
            int r  = f >> 2;                  // 0..127
            int c4 = (f & 3) * 4;             // 0,4,8,12
            float4 av = *reinterpret_cast<const float4*>(
                Ap + (size_t)(row0 + r) * K + k0 + c4);
            As[c4+0][r] = av.x; As[c4+1][r] = av.y;
            As[c4+2][r] = av.z; As[c4+3][r] = av.w;
            float4 wv = *reinterpret_cast<const float4*>(
                W + (size_t)(col0 + r) * K + k0 + c4);
            Ws[c4+0][r] = wv.x; Ws[c4+1][r] = wv.y;
            Ws[c4+2][r] = wv.z; Ws[c4+3][r] = wv.w;
        }
        __syncthreads();

        #pragma unroll
        for (int kk = 0; kk < 16; ++kk) {
            ulonglong2 a01 = *reinterpret_cast<const ulonglong2*>(&As[kk][ty*8]);
            ulonglong2 a23 = *reinterpret_cast<const ulonglong2*>(&As[kk][ty*8+4]);
            float4 w0 = *reinterpret_cast<const float4*>(&Ws[kk][tx*8]);
            float4 w1 = *reinterpret_cast<const float4*>(&Ws[kk][tx*8+4]);
            unsigned long long ar[4] = {a01.x, a01.y, a23.x, a23.y};
            float wf[8] = {w0.x, w0.y, w0.z, w0.w, w1.x, w1.y, w1.z, w1.w};
            #pragma unroll
            for (int j = 0; j < 8; ++j) {
                unsigned long long wb = pack2(wf[j], wf[j]);
                #pragma unroll
                for (int i2 = 0; i2 < 4; ++i2)
                    acc[i2][j] = fma2(ar[i2], wb, acc[i2][j]);
            }
        }
        __syncthreads();
    }

    // unpack into row-major register tile
    float Cv[8][8];
    #pragma unroll
    for (int i2 = 0; i2 < 4; ++i2)
        #pragma unroll
        for (int j = 0; j < 8; ++j) {
            float2 t = unpack2(acc[i2][j]);
            Cv[2*i2  ][j] = t.x;
            Cv[2*i2+1][j] = t.y;
        }

    #pragma unroll
    for (int i = 0; i < 8; ++i) {
        const int grow = row0 + ty * 8 + i;
        if constexpr (MODE == 0) {
            #pragma unroll
            for (int j = 0; j < 8; j += 4) {
                float4 o = make_float4(Cv[i][j], Cv[i][j+1], Cv[i][j+2], Cv[i][j+3]);
                *reinterpret_cast<float4*>(C + (size_t)grow * N + col0 + tx*8 + j) = o;
            }
        } else {
            const int b = grow >> 11;           // /S_
            const int s = grow & (S_ - 1);
            const int gcol0 = col0 + tx * 8;    // all 8 cols within one 64-head
            if constexpr (MODE == 1 || MODE == 2) {
                const int head = gcol0 >> 6;
                const int d0   = gcol0 & 63;    // even
                const int hh   = head >> 1;
                const int comp = head & 1;
                float* dst;
                if constexpr (MODE == 1)
                    dst = g_q + ((((size_t)b*H_   + hh)*2 + comp)*S_ + s)*D_ + d0;
                else
                    dst = g_k + ((((size_t)b*HKV_ + hh)*2 + comp)*S_ + s)*D_ + d0;
                const float* cr = cosp + (size_t)s * 32;
                const float* sr = sinp + (size_t)s * 32;
                #pragma unroll
                for (int jp = 0; jp < 4; ++jp) {
                    float c  = cr[(d0 >> 1) + jp];
                    float sn = sr[(d0 >> 1) + jp];
                    float x1 = Cv[i][2*jp], x2 = Cv[i][2*jp+1];
                    dst[2*jp  ] = x1*c  - x2*sn;
                    dst[2*jp+1] = x1*sn + x2*c;
                }
            } else {  // MODE 3: V, cols = hk*128 + c
                const int hk = gcol0 >> 7;
                const int cc = gcol0 & 127;
                float* dst = g_v + (((size_t)b*HKV_ + hk)*S_ + s)*128 + cc;
                #pragma unroll
                for (int j = 0; j < 8; j += 4)
                    *reinterpret_cast<float4*>(dst + j) =
                        make_float4(Cv[i][j], Cv[i][j+1], Cv[i][j+2], Cv[i][j+3]);
            }
        }
    }
}

// ============================================================================
// Causal flash attention, fp32, one (b, h, component) per blockIdx.(z,y).
// BM=64 queries, BN=64 keys per tile, D=64, DV=128, 256 threads.
// ============================================================================
#define QST 68
#define VST 132
#define FLASH_SMEM_FLOATS (64*QST*3 + 64*VST)
#define FLASH_SMEM_BYTES  (FLASH_SMEM_FLOATS * 4)

__global__ __launch_bounds__(256)
void flash_k()
{
    extern __shared__ float sm[];
    float* Qs = sm;                         // [d][r]   64 x 68
    float* Ks = sm + 64*QST;                // [d][c]   64 x 68
    float* Vs = sm + 2*64*QST;              // [c][cv]  64 x 132
    float* Ps = sm + 2*64*QST + 64*VST;     // [r][c]   64 x 68

    const int qt = blockIdx.x;              // 0..31
    const int h  = blockIdx.y >> 1;
    const int j  = blockIdx.y & 1;
    const int b  = blockIdx.z;

    const float* qp = g_q + ((((size_t)b*H_   + h     )*2 + j)*S_ + (size_t)qt*64)*D_;
    const float* kp = g_k + ((((size_t)b*HKV_ + (h>>1))*2 + j)*S_)*D_;
    const float* vp = g_v + ((( (size_t)b*HKV_ + (h>>1))*S_))*128;
    float* op = (j == 0 ? g_a1 : g_a2) + (((size_t)b*H_ + h)*S_ + (size_t)qt*64)*128;

    const int tid = threadIdx.x;
    const int tx  = tid & 15;   // key cols 4*tx..   / out cols 8*tx..
    const int ty  = tid >> 4;   // query rows 4*ty..

    // load Q tile transposed: Qs[d][r]
    #pragma unroll
    for (int it = 0; it < 4; ++it) {
        int f = tid + it*256;         // 0..1023
        int r = f >> 4, d4 = (f & 15) * 4;
        float4 v = *reinterpret_cast<const float4*>(qp + (size_t)r*64 + d4);
        Qs[(d4+0)*QST + r] = v.x; Qs[(d4+1)*QST + r] = v.y;
        Qs[(d4+2)*QST + r] = v.z; Qs[(d4+3)*QST + r] = v.w;
    }

    unsigned long long o2[4][4];    // rows(4) x col-pairs(4) of 128-wide output
    #pragma unroll
    for (int i = 0; i < 4; ++i)
        #pragma unroll
        for (int j2 = 0; j2 < 4; ++j2) o2[i][j2] = 0ULL;
    float m[4], l[4];
    #pragma unroll
    for (int i = 0; i < 4; ++i) { m[i] = NEGBIG; l[i] = 0.0f; }

    for (int n = 0; n <= qt; ++n) {
        __syncthreads();   // protect Ks/Vs/Ps reuse
        #pragma unroll
        for (int it = 0; it < 4; ++it) {
            int f = tid + it*256;
            int r = f >> 4, d4 = (f & 15) * 4;
            float4 v = *reinterpret_cast<const float4*>(kp + (size_t)(n*64 + r)*64 + d4);
            Ks[(d4+0)*QST + r] = v.x; Ks[(d4+1)*QST + r] = v.y;
            Ks[(d4+2)*QST + r] = v.z; Ks[(d4+3)*QST + r] = v.w;
        }
        #pragma unroll
        for (int it = 0; it < 8; ++it) {
            int f = tid + it*256;
            int r = f >> 5, c4 = (f & 31) * 4;
            *reinterpret_cast<float4*>(&Vs[r*VST + c4]) =
                *reinterpret_cast<const float4*>(vp + (size_t)(n*64 + r)*128 + c4);
        }
        __syncthreads();

        // S = Q K^T  (rows 4*ty.., cols 4*tx..), packed pairs along cols
        unsigned long long s2[4][2];
        #pragma unroll
        for (int i = 0; i < 4; ++i) { s2[i][0] = 0ULL; s2[i][1] = 0ULL; }
        #pragma unroll 4
        for (int d = 0; d < 64; ++d) {
            ulonglong2 kk2 = *reinterpret_cast<const ulonglong2*>(&Ks[d*QST + tx*4]);
            float4 qv = *reinterpret_cast<const float4*>(&Qs[d*QST + ty*4]);
            float qf[4] = {qv.x, qv.y, qv.z, qv.w};
            #pragma unroll
            for (int i = 0; i < 4; ++i) {
                unsigned long long qb = pack2(qf[i], qf[i]);
                s2[i][0] = fma2(qb, kk2.x, s2[i][0]);
                s2[i][1] = fma2(qb, kk2.y, s2[i][1]);
            }
        }

        const int qi0 = qt*64 + ty*4;
        const int kj0 = n *64 + tx*4;
        float sv[4][4];
        #pragma unroll
        for (int i = 0; i < 4; ++i) {
            float2 t0 = unpack2(s2[i][0]);
            float2 t1 = unpack2(s2[i][1]);
            sv[i][0] = t0.x * SCALE_; sv[i][1] = t0.y * SCALE_;
            sv[i][2] = t1.x * SCALE_; sv[i][3] = t1.y * SCALE_;
            #pragma unroll
            for (int jj = 0; jj < 4; ++jj)
                if (kj0 + jj > qi0 + i) sv[i][jj] = NEGBIG;
        }

        // online softmax (row stats reduced across the 16 tx lanes)
        #pragma unroll
        for (int i = 0; i < 4; ++i) {
            float mx = fmaxf(fmaxf(sv[i][0], sv[i][1]), fmaxf(sv[i][2], sv[i][3]));
            mx = fmaxf(mx, __shfl_xor_sync(0xffffffffu, mx, 8));
            mx = fmaxf(mx, __shfl_xor_sync(0xffffffffu, mx, 4));
            mx = fmaxf(mx, __shfl_xor_sync(0xffffffffu, mx, 2));
            mx = fmaxf(mx, __shfl_xor_sync(0xffffffffu, mx, 1));
            float mn   = fmaxf(m[i], mx);
            float corr = __expf(m[i] - mn);
            m[i] = mn;
            float srow = 0.0f;
            #pragma unroll
            for (int jj = 0; jj < 4; ++jj) {
                float p = __expf(sv[i][jj] - mn);
                Ps[(ty*4 + i)*QST + tx*4 + jj] = p;
                srow += p;
            }
            srow += __shfl_xor_sync(0xffffffffu, srow, 8);
            srow += __shfl_xor_sync(0xffffffffu, srow, 4);
            srow += __shfl_xor_sync(0xffffffffu, srow, 2);
            srow += __shfl_xor_sync(0xffffffffu, srow, 1);
            l[i] = l[i] * corr + srow;
            unsigned long long c2 = pack2(corr, corr);
            #pragma unroll
            for (int j2 = 0; j2 < 4; ++j2) o2[i][j2] = mul2(o2[i][j2], c2);
        }
        __syncthreads();

        // O += P V
        #pragma unroll 2
        for (int c = 0; c < 64; ++c) {
            ulonglong2 v01 = *reinterpret_cast<const ulonglong2*>(&Vs[c*VST + tx*8]);
            ulonglong2 v23 = *reinterpret_cast<const ulonglong2*>(&Vs[c*VST + tx*8 + 4]);
            unsigned long long vv[4] = {v01.x, v01.y, v23.x, v23.y};
            #pragma unroll
            for (int i = 0; i < 4; ++i) {
                float p = Ps[(ty*4 + i)*QST + c];
                unsigned long long pb = pack2(p, p);
                #pragma unroll
                for (int j2 = 0; j2 < 4; ++j2)
                    o2[i][j2] = fma2(pb, vv[j2], o2[i][j2]);
            }
        }
    }

    #pragma unroll
    for (int i = 0; i < 4; ++i) {
        float inv = 1.0f / l[i];
        float2 p0 = unpack2(o2[i][0]), p1 = unpack2(o2[i][1]);
        float2 p2 = unpack2(o2[i][2]), p3 = unpack2(o2[i][3]);
        float4 w0 = make_float4(p0.x*inv, p0.y*inv, p1.x*inv, p1.y*inv);
        float4 w1 = make_float4(p2.x*inv, p2.y*inv, p3.x*inv, p3.y*inv);
        *reinterpret_cast<float4*>(op + (size_t)(ty*4 + i)*128 + tx*8    ) = w0;
        *reinterpret_cast<float4*>(op + (size_t)(ty*4 + i)*128 + tx*8 + 4) = w1;
    }
}

// ============================================================================
// lambda scalar: exp(sum q1*k1) - exp(sum q2*k2) + lambda_init
// ============================================================================
__global__ void lam_k(const float* __restrict__ q1, const float* __restrict__ k1,
                      const float* __restrict__ q2, const float* __restrict__ k2)
{
    int t = threadIdx.x;
    float s1 = q1[t]*k1[t] + q1[t+32]*k1[t+32];
    float s2 = q2[t]*k2[t] + q2[t+32]*k2[t+32];
    #pragma unroll
    for (int off = 16; off; off >>= 1) {
        s1 += __shfl_xor_sync(0xffffffffu, s1, off);
        s2 += __shfl_xor_sync(0xffffffffu, s2, off);
    }
    if (t == 0) g_lam = expf(s1) - expf(s2) + kLambdaInit;
}

// ============================================================================
// combine: a = a1 - lam*a2; RMSNorm over 128; * subln_w * (1-lambda_init);
// scatter into [(b,s)][h*128+c] for the output GEMM. One warp per (b,h,s) row.
// ============================================================================
__global__ __launch_bounds__(256)
void combine_k(const float* __restrict__ subw)
{
    const int warp = threadIdx.x >> 5;
    const int lane = threadIdx.x & 31;
    const size_t r = (size_t)blockIdx.x * 8 + warp;     // over B*H*S
    const float lam = g_lam;

    float4 a1 = *reinterpret_cast<const float4*>(&g_a1[r*128 + lane*4]);
    float4 a2 = *reinterpret_cast<const float4*>(&g_a2[r*128 + lane*4]);
    float v0 = a1.x - lam*a2.x;
    float v1 = a1.y - lam*a2.y;
    float v2 = a1.z - lam*a2.z;
    float v3 = a1.w - lam*a2.w;

    float ss = v0*v0 + v1*v1 + v2*v2 + v3*v3;
    #pragma unroll
    for (int off = 16; off; off >>= 1)
        ss += __shfl_xor_sync(0xffffffffu, ss, off);

    float sc = rsqrtf(ss * (1.0f/128.0f) + 1e-5f) * kOneMinusLI;
    float4 w = *reinterpret_cast<const float4*>(&subw[lane*4]);

    const int s  = (int)(r & (S_ - 1));
    const int bh = (int)(r >> 11);
    const int b  = bh >> 4;
    const int hh = bh & 15;

    float4 o = make_float4(v0*sc*w.x, v1*sc*w.y, v2*sc*w.z, v3*sc*w.w);
    *reinterpret_cast<float4*>(&g_ac[((size_t)(b*S_ + s))*E_ + hh*128 + lane*4]) = o;
}

// ============================================================================
// launcher
// ============================================================================
extern "C" void kernel_launch(void* const* d_in, const int* in_sizes, int n_in,
                              void* d_out, int out_size)
{
    const float* x    = (const float*)d_in[0];
    const float* cosp = (const float*)d_in[1];
    const float* sinp = (const float*)d_in[2];
    const float* Wq   = (const float*)d_in[3];
    const float* Wk   = (const float*)d_in[4];
    const float* Wv   = (const float*)d_in[5];
    const float* Wo   = (const float*)d_in[6];
    const float* lq1  = (const float*)d_in[7];
    const float* lk1  = (const float*)d_in[8];
    const float* lq2  = (const float*)d_in[9];
    const float* lk2  = (const float*)d_in[10];
    const float* subw = (const float*)d_in[11];
    float* out = (float*)d_out;

    cudaFuncSetAttribute(flash_k, cudaFuncAttributeMaxDynamicSharedMemorySize,
                         FLASH_SMEM_BYTES);

    // projections (rotary fused into Q/K epilogues, layout scatter fused into all)
    sgemm_k<1, 2048><<<dim3(16, 32), 256>>>(x, Wq, nullptr, cosp, sinp);
    sgemm_k<2, 1024><<<dim3( 8, 32), 256>>>(x, Wk, nullptr, cosp, sinp);
    sgemm_k<3, 1024><<<dim3( 8, 32), 256>>>(x, Wv, nullptr, nullptr, nullptr);

    lam_k<<<1, 32>>>(lq1, lk1, lq2, lk2);

    // 64 causal flash instances: (qtile=32, h*2+comp=32, b=2)
    flash_k<<<dim3(32, 32, 2), 256, FLASH_SMEM_BYTES>>>();

    // differential combine + RMSNorm
    combine_k<<<(B_*H_*S_)/8, 256>>>(subw);

    // output projection
    sgemm_k<0, 2048><<<dim3(16, 32), 256>>>(nullptr, Wo, out, nullptr, nullptr);
}